// round 1
// baseline (speedup 1.0000x reference)
#include <cuda_runtime.h>

// ---------------- problem constants ----------------
#define BB 16
#define TT 12
#define FF 32
// Layer1: 48x48x3 -> 47x46x32 (valid 2x3), Layer2: 47x46x32 -> 46x44x32
#define H1 48
#define W1 48
#define C1 3
#define HO1 47
#define WO1 46
#define H2 47
#define W2 46
#define C2 32
#define HO2 46
#define WO2 44
// pooled: 23x22, flat = 12*23*22*32 = 194304
#define FLAT 194304
#define NCHUNK 256
#define CHUNK 759   // 256*759 = 194304 exactly

// ---------------- device scratch (no allocation allowed) ----------------
__device__ float g_h1[(long)TT * BB * HO1 * WO1 * FF];      // 53.1 MB
__device__ float g_h2[(long)TT * BB * HO2 * WO2 * FF];      // 49.7 MB
__device__ float g_c[BB * HO1 * WO1 * FF];                  // 4.4 MB (reused for both layers)
__device__ float g_hzero[BB * HO1 * WO1 * FF];              // zeros (h0)
__device__ float g_pool[BB * FLAT];
__device__ float g_part[NCHUNK * BB * 10];
__device__ float4 g_Wr1[6 * C1 * 32];
__device__ float4 g_Ur1[6 * 32 * 32];
__device__ float4 g_Wr2[6 * 32 * 32];
__device__ float4 g_Ur2[6 * 32 * 32];

__device__ __forceinline__ float hsig(float x) {
    return fminf(fmaxf(fmaf(0.2f, x, 0.5f), 0.0f), 1.0f);
}

// Reorder conv weights [k(6)][cin][128] -> float4 per (k,cin,f): {w_i, w_f, w_c, w_o}
__global__ void reorder_kernel(const float* __restrict__ src, float4* __restrict__ dst, int n) {
    int idx = blockIdx.x * blockDim.x + threadIdx.x;
    if (idx < n) {
        int f = idx & 31;
        int kc = idx >> 5;
        const float* s = src + kc * 128;
        dst[idx] = make_float4(s[f], s[32 + f], s[64 + f], s[96 + f]);
    }
}

// One fused ConvLSTM timestep.
// Grid: (tilesX, tilesY, B). Block: 256 = 8 warps; warp -> output row, lane -> channel f.
// Each thread computes 8 output columns x 4 gates.
template <int CIN>
__global__ void __launch_bounds__(256, 2) step_kernel(
    const float* __restrict__ xin, int xbstride, int H, int W,
    const float* __restrict__ hprev,
    float* __restrict__ cbuf,
    float* __restrict__ hout,
    const float4* __restrict__ Wr, const float4* __restrict__ Ur,
    const float* __restrict__ bias,
    int Ho, int Wo)
{
    __shared__ float xs[9][10][CIN]; // input rows y0..y0+8, cols x0..x0+9
    __shared__ float hs[9][10][32];  // h rows y0..y0+8, cols x0-1..x0+8 (zero-padded)

    const int tid = threadIdx.x;
    const int f = tid & 31;
    const int wp = tid >> 5;            // warp id = row within tile
    const int b = blockIdx.z;
    const int y0 = blockIdx.y * 8;
    const int x0 = blockIdx.x * 8;
    const int hb = Ho * Wo * 32;

    // ---- stage x patch ----
    for (int i = tid; i < 9 * 10 * CIN; i += 256) {
        int ci = i % CIN; int t2 = i / CIN;
        int cx = t2 % 10; int r = t2 / 10;
        int gy = y0 + r, gx = x0 + cx;
        float v = 0.0f;
        if (gy < H && gx < W)
            v = xin[(long)b * xbstride + (gy * W + gx) * CIN + ci];
        xs[r][cx][ci] = v;
    }
    // ---- stage h patch (SAME padding: top 0 / bottom 1, left 1 / right 1) ----
    for (int i = tid; i < 9 * 10 * 32; i += 256) {
        int ci = i & 31; int t2 = i >> 5;
        int cx = t2 % 10; int r = t2 / 10;
        int gy = y0 + r, gx = x0 + cx - 1;
        float v = 0.0f;
        if (gy < Ho && gx >= 0 && gx < Wo)
            v = hprev[(long)b * hb + (gy * Wo + gx) * 32 + ci];
        hs[r][cx][ci] = v;
    }
    __syncthreads();

    float4 acc[8];
    float4 bv = make_float4(bias[f], bias[32 + f], bias[64 + f], bias[96 + f]);
#pragma unroll
    for (int p = 0; p < 8; p++) acc[p] = bv;

    // ---- input conv (VALID): out(y,x) reads x rows y..y+1, cols x..x+2 ----
#pragma unroll
    for (int k = 0; k < 6; k++) {
        const int dy = k / 3, dx = k % 3;
#pragma unroll 4
        for (int ci = 0; ci < CIN; ci++) {
            float4 w = Wr[(k * CIN + ci) * 32 + f];
#pragma unroll
            for (int p = 0; p < 8; p++) {
                float v = xs[wp + dy][p + dx][ci];
                acc[p].x = fmaf(v, w.x, acc[p].x);
                acc[p].y = fmaf(v, w.y, acc[p].y);
                acc[p].z = fmaf(v, w.z, acc[p].z);
                acc[p].w = fmaf(v, w.w, acc[p].w);
            }
        }
    }
    // ---- recurrent conv (SAME): out(y,x) reads h rows y..y+1, cols x-1..x+1 ----
#pragma unroll
    for (int k = 0; k < 6; k++) {
        const int dy = k / 3, dx = k % 3;
#pragma unroll 4
        for (int ci = 0; ci < 32; ci++) {
            float4 w = Ur[(k * 32 + ci) * 32 + f];
#pragma unroll
            for (int p = 0; p < 8; p++) {
                float v = hs[wp + dy][p + dx][ci]; // hs col 0 == x0-1
                acc[p].x = fmaf(v, w.x, acc[p].x);
                acc[p].y = fmaf(v, w.y, acc[p].y);
                acc[p].z = fmaf(v, w.z, acc[p].z);
                acc[p].w = fmaf(v, w.w, acc[p].w);
            }
        }
    }

    // ---- gates + state update ----
    const int y = y0 + wp;
    if (y < Ho) {
#pragma unroll
        for (int p = 0; p < 8; p++) {
            int gx = x0 + p;
            if (gx < Wo) {
                long o = (long)b * hb + (y * Wo + gx) * 32 + f;
                float cold = cbuf[o];
                float ig = hsig(acc[p].x);
                float fg = hsig(acc[p].y);
                float cn = fmaf(fg, cold, ig * fmaxf(acc[p].z, 0.0f));
                cbuf[o] = cn;
                hout[o] = hsig(acc[p].w) * fmaxf(cn, 0.0f);
            }
        }
    }
}

// MaxPool (1,2,2) over h2 stored [T][B][46][44][32] -> pool [B][T][23][22][32] (flatten order)
__global__ void pool_kernel(const float* __restrict__ h2, float* __restrict__ pout) {
    int idx = blockIdx.x * blockDim.x + threadIdx.x;
    if (idx >= BB * TT * 23 * 22 * 32) return;
    int c = idx & 31; int t2 = idx >> 5;
    int pw = t2 % 22; t2 /= 22;
    int ph = t2 % 23; t2 /= 23;
    int t = t2 % TT; int b = t2 / TT;
    const float* base = h2 + (((long)(t * BB + b) * HO2 + 2 * ph) * WO2 + 2 * pw) * 32 + c;
    float m = fmaxf(fmaxf(base[0], base[32]),
                    fmaxf(base[WO2 * 32], base[WO2 * 32 + 32]));
    pout[idx] = m;
}

// Dense1 partial sums: grid (NCHUNK, B), block 128. part[(ch*B+b)*10+j]
__global__ void __launch_bounds__(128) dense_part_kernel(
    const float* __restrict__ pool, const float* __restrict__ Wd1, float* __restrict__ part)
{
    int ch = blockIdx.x, b = blockIdx.y;
    int start = ch * CHUNK;
    float s[10];
#pragma unroll
    for (int j = 0; j < 10; j++) s[j] = 0.0f;
    for (int i = start + threadIdx.x; i < start + CHUNK; i += 128) {
        float v = pool[b * FLAT + i];
        const float* w = Wd1 + (long)i * 10;
#pragma unroll
        for (int j = 0; j < 10; j++) s[j] = fmaf(v, w[j], s[j]);
    }
    __shared__ float red[10][128];
#pragma unroll
    for (int j = 0; j < 10; j++) red[j][threadIdx.x] = s[j];
    __syncthreads();
    for (int off = 64; off > 0; off >>= 1) {
        if (threadIdx.x < off) {
#pragma unroll
            for (int j = 0; j < 10; j++)
                red[j][threadIdx.x] += red[j][threadIdx.x + off];
        }
        __syncthreads();
    }
    if (threadIdx.x < 10)
        part[(ch * BB + b) * 10 + threadIdx.x] = red[threadIdx.x][0];
}

// Reduce partials + dense2. One block.
__global__ void final_kernel(const float* __restrict__ part,
                             const float* __restrict__ bd1,
                             const float* __restrict__ Wd2,
                             const float* __restrict__ bd2,
                             float* __restrict__ out)
{
    __shared__ float sd1[BB][10];
    int tid = threadIdx.x;
    if (tid < BB * 10) {
        int b = tid / 10, j = tid % 10;
        float s = bd1[j];
        for (int ch = 0; ch < NCHUNK; ch++)
            s += part[(ch * BB + b) * 10 + j];
        sd1[b][j] = s;
    }
    __syncthreads();
    if (tid < BB) {
        float o = bd2[0];
#pragma unroll
        for (int j = 0; j < 10; j++)
            o = fmaf(sd1[tid][j], Wd2[j], o);
        out[tid] = o;
    }
}

// ---------------- launcher ----------------
extern "C" void kernel_launch(void* const* d_in, const int* in_sizes, int n_in,
                              void* d_out, int out_size) {
    const float* x   = (const float*)d_in[0];
    const float* W1p = (const float*)d_in[1];
    const float* U1p = (const float*)d_in[2];
    const float* b1p = (const float*)d_in[3];
    const float* W2p = (const float*)d_in[4];
    const float* U2p = (const float*)d_in[5];
    const float* b2p = (const float*)d_in[6];
    const float* Wd1 = (const float*)d_in[7];
    const float* bd1 = (const float*)d_in[8];
    const float* Wd2 = (const float*)d_in[9];
    const float* bd2 = (const float*)d_in[10];
    float* out = (float*)d_out;

    float *h1, *h2, *cb, *hz, *pool, *part;
    float4 *wr1, *ur1, *wr2, *ur2;
    cudaGetSymbolAddress((void**)&h1, g_h1);
    cudaGetSymbolAddress((void**)&h2, g_h2);
    cudaGetSymbolAddress((void**)&cb, g_c);
    cudaGetSymbolAddress((void**)&hz, g_hzero);
    cudaGetSymbolAddress((void**)&pool, g_pool);
    cudaGetSymbolAddress((void**)&part, g_part);
    cudaGetSymbolAddress((void**)&wr1, g_Wr1);
    cudaGetSymbolAddress((void**)&ur1, g_Ur1);
    cudaGetSymbolAddress((void**)&wr2, g_Wr2);
    cudaGetSymbolAddress((void**)&ur2, g_Ur2);

    reorder_kernel<<<(6 * C1 * 32 + 255) / 256, 256>>>(W1p, wr1, 6 * C1 * 32);
    reorder_kernel<<<(6 * 32 * 32 + 255) / 256, 256>>>(U1p, ur1, 6 * 32 * 32);
    reorder_kernel<<<(6 * 32 * 32 + 255) / 256, 256>>>(W2p, wr2, 6 * 32 * 32);
    reorder_kernel<<<(6 * 32 * 32 + 255) / 256, 256>>>(U2p, ur2, 6 * 32 * 32);

    cudaMemsetAsync(hz, 0, sizeof(float) * BB * HO1 * WO1 * FF, 0);
    cudaMemsetAsync(cb, 0, sizeof(float) * BB * HO1 * WO1 * FF, 0);

    dim3 blk(256);
    dim3 g1((WO1 + 7) / 8, (HO1 + 7) / 8, BB);
    const long h1slice = (long)BB * HO1 * WO1 * FF;
    for (int t = 0; t < TT; t++) {
        const float* xt = x + (long)t * H1 * W1 * C1;
        const float* hp = t ? (h1 + (t - 1) * h1slice) : hz;
        step_kernel<C1><<<g1, blk>>>(xt, TT * H1 * W1 * C1, H1, W1,
                                     hp, cb, h1 + t * h1slice,
                                     wr1, ur1, b1p, HO1, WO1);
    }

    cudaMemsetAsync(cb, 0, sizeof(float) * BB * HO2 * WO2 * FF, 0);
    dim3 g2((WO2 + 7) / 8, (HO2 + 7) / 8, BB);
    const long h2slice = (long)BB * HO2 * WO2 * FF;
    for (int t = 0; t < TT; t++) {
        const float* xt = h1 + t * h1slice;
        const float* hp = t ? (h2 + (t - 1) * h2slice) : hz;
        step_kernel<C2><<<g2, blk>>>(xt, HO1 * WO1 * FF, H2, W2,
                                     hp, cb, h2 + t * h2slice,
                                     wr2, ur2, b2p, HO2, WO2);
    }

    int npool = BB * TT * 23 * 22 * 32;
    pool_kernel<<<(npool + 255) / 256, 256>>>(h2, pool);
    dense_part_kernel<<<dim3(NCHUNK, BB), 128>>>(pool, Wd1, part);
    final_kernel<<<1, 256>>>(part, bd1, Wd2, bd2, out);
}